// round 16
// baseline (speedup 1.0000x reference)
#include <cuda_runtime.h>
#include <cuda_bf16.h>
#include <math.h>

// Problem dims (fixed by the reference)
#define Bz      8
#define Tz      4096
#define Cz      256
#define HIDz    1024
#define BTz     (Bz*Tz)          // 32768 tokens
#define CHUNK   64
#define NCHUNK  (Tz/CHUNK)       // 64
#define NKVR    768              // k|v|r packed width
#define NFF1    1280             // ffn_k|ffn_r packed width

typedef unsigned short bf16r;    // raw bf16 bits

__device__ __forceinline__ bf16r f2b_one(float f) {
    __nv_bfloat16 b = __float2bfloat16(f);
    return *(bf16r*)&b;
}
__device__ __forceinline__ float b2f(bf16r r) {
    return __uint_as_float((unsigned)r << 16);
}

// ---------------- scratch (static __device__, no allocs) ----------------
__device__ bf16r g_kvrb[(size_t)BTz*NKVR]; // bf16 k|v|r(pre-sigmoid), 48MB
__device__ bf16r g_srb [(size_t)BTz*Cz];   // FFN gate (sigmoid), bf16
__device__ bf16r g_hb  [(size_t)BTz*Cz];   // bf16 LN1 out, later bf16(sr*y)
__device__ bf16r g_h2b [(size_t)BTz*Cz];   // bf16 LN2 out
__device__ bf16r g_kkb [(size_t)BTz*HIDz]; // bf16 FFN hidden
__device__ float g_cA [Bz*Cz*NCHUNK];
__device__ float g_cB [Bz*Cz*NCHUNK];
__device__ float g_a0 [Bz*Cz*NCHUNK];
__device__ float g_b0 [Bz*Cz*NCHUNK];
// packed bf16 weights, TRANSPOSED: [N, K] row-major
__device__ bf16r g_wkvr[NKVR*Cz];          // (Wk|Wv|Wr)^T : [768,256]
__device__ bf16r g_wf1 [NFF1*Cz];          // (Wk_ffn|Wr_ffn)^T : [1280,256]
__device__ bf16r g_wo  [Cz*Cz];            // Wo^T : [256,256]
__device__ bf16r g_wvf [Cz*HIDz];          // Wv_ffn^T : [256,1024]

// ---------------- merged weight pack: kvr | wf1 | wo | wvf ----------------
#define PK_KVR (NKVR*Cz)
#define PK_F1  (NFF1*Cz)
#define PK_WO  (Cz*Cz)
#define PK_WVF (HIDz*Cz)
#define PK_ALL (PK_KVR + PK_F1 + PK_WO + PK_WVF)   // 851968
__global__ void pack_all_kernel(const float* __restrict__ Wk,
                                const float* __restrict__ Wv,
                                const float* __restrict__ Wr,
                                const float* __restrict__ Wkf,
                                const float* __restrict__ Wrf,
                                const float* __restrict__ Wo,
                                const float* __restrict__ Wvf,
                                bf16r* __restrict__ okvr,
                                bf16r* __restrict__ of1,
                                bf16r* __restrict__ owo,
                                bf16r* __restrict__ owvf)
{
    int i = blockIdx.x * 256 + threadIdx.x;
    if (i < PK_KVR) {
        int n = i / Cz, k = i % Cz;
        float v = (n < 256) ? Wk[k * 256 + n]
                : (n < 512) ? Wv[k * 256 + (n - 256)]
                            : Wr[k * 256 + (n - 512)];
        okvr[i] = f2b_one(v);
    } else if (i < PK_KVR + PK_F1) {
        int j = i - PK_KVR;
        int n = j / Cz, k = j % Cz;
        float v = (n < 1024) ? Wkf[k * 1024 + n] : Wrf[k * 256 + (n - 1024)];
        of1[j] = f2b_one(v);
    } else if (i < PK_KVR + PK_F1 + PK_WO) {
        int j = i - PK_KVR - PK_F1;
        int n = j / Cz, k = j % Cz;
        owo[j] = f2b_one(Wo[k * 256 + n]);
    } else {
        int j = i - PK_KVR - PK_F1 - PK_WO;
        int n = j / HIDz, k = j % HIDz;
        owvf[j] = f2b_one(Wvf[(size_t)k * 256 + n]);
    }
}

// ---------------- LayerNorm: one WARP per token, 4 tokens/block ----------------
__global__ void __launch_bounds__(128)
ln_kernel(const float* __restrict__ x,
          const float* __restrict__ g,
          const float* __restrict__ b,
          bf16r* __restrict__ out)
{
    int lane = threadIdx.x & 31;
    int wid  = threadIdx.x >> 5;
    size_t base = ((size_t)blockIdx.x * 4 + wid) * Cz + lane * 8;
    float4 v0 = *(const float4*)(x + base);
    float4 v1 = *(const float4*)(x + base + 4);
    float s  = v0.x + v0.y + v0.z + v0.w + v1.x + v1.y + v1.z + v1.w;
    float s2 = v0.x*v0.x + v0.y*v0.y + v0.z*v0.z + v0.w*v0.w
             + v1.x*v1.x + v1.y*v1.y + v1.z*v1.z + v1.w*v1.w;
    #pragma unroll
    for (int off = 16; off; off >>= 1) {
        s  += __shfl_xor_sync(0xffffffffu, s,  off);
        s2 += __shfl_xor_sync(0xffffffffu, s2, off);
    }
    float m   = s  * (1.0f / Cz);
    float var = s2 * (1.0f / Cz) - m * m;
    float rs  = rsqrtf(var + 1e-5f);
    float4 g0 = *(const float4*)(g + lane * 8);
    float4 g1 = *(const float4*)(g + lane * 8 + 4);
    float4 b0 = *(const float4*)(b + lane * 8);
    float4 b1 = *(const float4*)(b + lane * 8 + 4);
    uint4 o;
    o.x = ((unsigned)f2b_one((v0.y - m) * rs * g0.y + b0.y) << 16) | f2b_one((v0.x - m) * rs * g0.x + b0.x);
    o.y = ((unsigned)f2b_one((v0.w - m) * rs * g0.w + b0.w) << 16) | f2b_one((v0.z - m) * rs * g0.z + b0.z);
    o.z = ((unsigned)f2b_one((v1.y - m) * rs * g1.y + b1.y) << 16) | f2b_one((v1.x - m) * rs * g1.x + b1.x);
    o.w = ((unsigned)f2b_one((v1.w - m) * rs * g1.w + b1.w) << 16) | f2b_one((v1.z - m) * rs * g1.z + b1.z);
    *(uint4*)(out + base) = o;
}

// ---------------- async-copy / ldmatrix helpers ----------------
__device__ __forceinline__ void cp16(void* sdst, const void* gsrc) {
    unsigned d = (unsigned)__cvta_generic_to_shared(sdst);
    asm volatile("cp.async.cg.shared.global [%0], [%1], 16;" :: "r"(d), "l"(gsrc));
}
__device__ __forceinline__ void ldsm_x4(unsigned& r0, unsigned& r1, unsigned& r2, unsigned& r3,
                                        const void* p) {
    unsigned a = (unsigned)__cvta_generic_to_shared(p);
    asm volatile("ldmatrix.sync.aligned.m8n8.x4.shared.b16 {%0,%1,%2,%3}, [%4];"
                 : "=r"(r0), "=r"(r1), "=r"(r2), "=r"(r3) : "r"(a));
}

#define GSM_STAGE 16384            // one 128x64 bf16 tile, 128B rows
#define GSM_TOTAL 65536            // A0,A1,B0,B1

// ---------------- GEMM variant A (R8 winner): 256 thr, warp tile 32x64 --------------
// Used for epilogue-heavy / small-N launches (Wo mode 3, FF2 mode 4).
__global__ void __launch_bounds__(256, 2)
gemm_w32_kernel(const bf16r* __restrict__ A,
                const bf16r* __restrict__ BT,
                void* __restrict__ outv,
                const float* __restrict__ res,
                const bf16r* __restrict__ gate,
                void* __restrict__ out2v,
                int K, int N, int mode)
{
    extern __shared__ char smem[];
    char* sA[2] = { smem,               smem + GSM_STAGE };
    char* sB[2] = { smem + 2*GSM_STAGE, smem + 3*GSM_STAGE };

    int tid  = threadIdx.x;
    int lane = tid & 31;
    int warp = tid >> 5;
    int wm = (warp & 3) * 32;
    int wn = (warp >> 2) * 64;
    int blockRow = blockIdx.x * 128;
    int blockCol = blockIdx.y * 128;

    const bf16r* Ab = A  + (size_t)blockRow * K;
    const bf16r* Bb = BT + (size_t)blockCol * K;

    float acc[2][8][4];
    #pragma unroll
    for (int i = 0; i < 2; i++)
        #pragma unroll
        for (int j = 0; j < 8; j++)
            #pragma unroll
            for (int l = 0; l < 4; l++) acc[i][j][l] = 0.f;

    int nk = K >> 6;

    #pragma unroll
    for (int it = 0; it < 4; it++) {
        int idx = tid + it * 256;
        int r = idx >> 3, c8 = idx & 7;
        unsigned so = (unsigned)r * 128u + (unsigned)((c8 ^ (r & 7)) * 16);
        cp16(sA[0] + so, Ab + (size_t)r * K + c8 * 8);
        cp16(sB[0] + so, Bb + (size_t)r * K + c8 * 8);
    }
    asm volatile("cp.async.commit_group;");

    int a_row = wm + (lane & 15);
    int a_half = lane >> 4;
    int b_grp = lane >> 3;
    int b_row = wn + (b_grp >> 1) * 8 + (lane & 7);
    int b_half = b_grp & 1;

    for (int kb = 0; kb < nk; kb++) {
        int buf = kb & 1;
        if (kb + 1 < nk) {
            int ko = (kb + 1) << 6;
            #pragma unroll
            for (int it = 0; it < 4; it++) {
                int idx = tid + it * 256;
                int r = idx >> 3, c8 = idx & 7;
                unsigned so = (unsigned)r * 128u + (unsigned)((c8 ^ (r & 7)) * 16);
                cp16(sA[buf ^ 1] + so, Ab + (size_t)r * K + ko + c8 * 8);
                cp16(sB[buf ^ 1] + so, Bb + (size_t)r * K + ko + c8 * 8);
            }
            asm volatile("cp.async.commit_group;");
            asm volatile("cp.async.wait_group 1;");
        } else {
            asm volatile("cp.async.wait_group 0;");
        }
        __syncthreads();

        #pragma unroll
        for (int k16 = 0; k16 < 4; k16++) {
            unsigned af[2][4], bfr[4][4];
            int ac8 = k16 * 2 + a_half;
            int bc8 = k16 * 2 + b_half;
            #pragma unroll
            for (int sm = 0; sm < 2; sm++) {
                int r = a_row + sm * 16;
                ldsm_x4(af[sm][0], af[sm][1], af[sm][2], af[sm][3],
                        sA[buf] + (unsigned)r * 128u + (unsigned)((ac8 ^ (r & 7)) * 16));
            }
            #pragma unroll
            for (int pr = 0; pr < 4; pr++) {
                int r = b_row + pr * 16;
                ldsm_x4(bfr[pr][0], bfr[pr][1], bfr[pr][2], bfr[pr][3],
                        sB[buf] + (unsigned)r * 128u + (unsigned)((bc8 ^ (r & 7)) * 16));
            }
            #pragma unroll
            for (int sm = 0; sm < 2; sm++)
                #pragma unroll
                for (int sn = 0; sn < 8; sn++) {
                    int pr = sn >> 1, q = (sn & 1) * 2;
                    asm volatile(
                        "mma.sync.aligned.m16n8k16.row.col.f32.bf16.bf16.f32 "
                        "{%0,%1,%2,%3}, {%4,%5,%6,%7}, {%8,%9}, {%0,%1,%2,%3};"
                        : "+f"(acc[sm][sn][0]), "+f"(acc[sm][sn][1]),
                          "+f"(acc[sm][sn][2]), "+f"(acc[sm][sn][3])
                        : "r"(af[sm][0]), "r"(af[sm][1]), "r"(af[sm][2]), "r"(af[sm][3]),
                          "r"(bfr[pr][q]), "r"(bfr[pr][q + 1]));
                }
        }
        if (kb + 1 < nk) __syncthreads();
    }

    #pragma unroll
    for (int sm = 0; sm < 2; sm++) {
        #pragma unroll
        for (int sn = 0; sn < 8; sn++) {
            int r0 = blockRow + wm + sm * 16 + (lane >> 2);
            int cc = blockCol + wn + sn * 8 + (lane & 3) * 2;
            #pragma unroll
            for (int half = 0; half < 2; half++) {
                int row = r0 + half * 8;
                float v0 = acc[sm][sn][half * 2 + 0];
                float v1 = acc[sm][sn][half * 2 + 1];
                if (mode == 3) {
                    size_t o = (size_t)row * N + cc;
                    v0 += res[o]; v1 += res[o + 1];
                    *(float2*)((float*)outv + o) = make_float2(v0, v1);
                } else { // mode 4
                    size_t o = (size_t)row * N + cc;
                    unsigned gp = *(const unsigned*)(gate + o);
                    v0 = res[o]     + b2f((bf16r)(gp & 0xFFFFu)) * v0;
                    v1 = res[o + 1] + b2f((bf16r)(gp >> 16))     * v1;
                    *(float2*)((float*)outv + o) = make_float2(v0, v1);
                }
            }
        }
    }
}

// ---------------- GEMM variant B (R9 mainloop): 128 thr, warp tile 64x64 ------------
// Used for mainloop-dominated big-N launches (KVR mode 0, FF1 mode 5).
__global__ void __launch_bounds__(128, 2)
gemm_w64_kernel(const bf16r* __restrict__ A,
                const bf16r* __restrict__ BT,
                void* __restrict__ outv,
                void* __restrict__ out2v,
                int K, int N, int mode)   // mode: 0 plain bf16, 5 split
{
    extern __shared__ char smem[];
    char* sA[2] = { smem,               smem + GSM_STAGE };
    char* sB[2] = { smem + 2*GSM_STAGE, smem + 3*GSM_STAGE };

    int tid  = threadIdx.x;
    int lane = tid & 31;
    int warp = tid >> 5;
    int wm = (warp & 1) * 64;
    int wn = (warp >> 1) * 64;
    int blockRow = blockIdx.x * 128;
    int blockCol = blockIdx.y * 128;

    const bf16r* Ab = A  + (size_t)blockRow * K;
    const bf16r* Bb = BT + (size_t)blockCol * K;

    float acc[4][8][4];
    #pragma unroll
    for (int i = 0; i < 4; i++)
        #pragma unroll
        for (int j = 0; j < 8; j++)
            #pragma unroll
            for (int l = 0; l < 4; l++) acc[i][j][l] = 0.f;

    int nk = K >> 6;

    #pragma unroll
    for (int it = 0; it < 8; it++) {
        int idx = tid + it * 128;
        int r = idx >> 3, c8 = idx & 7;
        unsigned so = (unsigned)r * 128u + (unsigned)((c8 ^ (r & 7)) * 16);
        cp16(sA[0] + so, Ab + (size_t)r * K + c8 * 8);
        cp16(sB[0] + so, Bb + (size_t)r * K + c8 * 8);
    }
    asm volatile("cp.async.commit_group;");

    int a_row = wm + (lane & 15);
    int a_half = lane >> 4;
    int b_grp = lane >> 3;
    int b_row = wn + (b_grp >> 1) * 8 + (lane & 7);
    int b_half = b_grp & 1;

    for (int kb = 0; kb < nk; kb++) {
        int buf = kb & 1;
        if (kb + 1 < nk) {
            int ko = (kb + 1) << 6;
            #pragma unroll
            for (int it = 0; it < 8; it++) {
                int idx = tid + it * 128;
                int r = idx >> 3, c8 = idx & 7;
                unsigned so = (unsigned)r * 128u + (unsigned)((c8 ^ (r & 7)) * 16);
                cp16(sA[buf ^ 1] + so, Ab + (size_t)r * K + ko + c8 * 8);
                cp16(sB[buf ^ 1] + so, Bb + (size_t)r * K + ko + c8 * 8);
            }
            asm volatile("cp.async.commit_group;");
            asm volatile("cp.async.wait_group 1;");
        } else {
            asm volatile("cp.async.wait_group 0;");
        }
        __syncthreads();

        #pragma unroll
        for (int k16 = 0; k16 < 4; k16++) {
            unsigned af[4][4], bfr[4][4];
            int ac8 = k16 * 2 + a_half;
            int bc8 = k16 * 2 + b_half;
            #pragma unroll
            for (int sm = 0; sm < 4; sm++) {
                int r = a_row + sm * 16;
                ldsm_x4(af[sm][0], af[sm][1], af[sm][2], af[sm][3],
                        sA[buf] + (unsigned)r * 128u + (unsigned)((ac8 ^ (r & 7)) * 16));
            }
            #pragma unroll
            for (int pr = 0; pr < 4; pr++) {
                int r = b_row + pr * 16;
                ldsm_x4(bfr[pr][0], bfr[pr][1], bfr[pr][2], bfr[pr][3],
                        sB[buf] + (unsigned)r * 128u + (unsigned)((bc8 ^ (r & 7)) * 16));
            }
            #pragma unroll
            for (int sm = 0; sm < 4; sm++)
                #pragma unroll
                for (int sn = 0; sn < 8; sn++) {
                    int pr = sn >> 1, q = (sn & 1) * 2;
                    asm volatile(
                        "mma.sync.aligned.m16n8k16.row.col.f32.bf16.bf16.f32 "
                        "{%0,%1,%2,%3}, {%4,%5,%6,%7}, {%8,%9}, {%0,%1,%2,%3};"
                        : "+f"(acc[sm][sn][0]), "+f"(acc[sm][sn][1]),
                          "+f"(acc[sm][sn][2]), "+f"(acc[sm][sn][3])
                        : "r"(af[sm][0]), "r"(af[sm][1]), "r"(af[sm][2]), "r"(af[sm][3]),
                          "r"(bfr[pr][q]), "r"(bfr[pr][q + 1]));
                }
        }
        if (kb + 1 < nk) __syncthreads();
    }

    #pragma unroll
    for (int sm = 0; sm < 4; sm++) {
        #pragma unroll
        for (int sn = 0; sn < 8; sn++) {
            int r0 = blockRow + wm + sm * 16 + (lane >> 2);
            int cc = blockCol + wn + sn * 8 + (lane & 3) * 2;
            #pragma unroll
            for (int half = 0; half < 2; half++) {
                int row = r0 + half * 8;
                float v0 = acc[sm][sn][half * 2 + 0];
                float v1 = acc[sm][sn][half * 2 + 1];
                if (mode == 0) {
                    size_t o = (size_t)row * N + cc;
                    unsigned pk = ((unsigned)f2b_one(v1) << 16) | f2b_one(v0);
                    *(unsigned*)((bf16r*)outv + o) = pk;
                } else { // mode 5 split
                    if (cc < 1024) {
                        float a0 = fmaxf(v0, 0.f), a1 = fmaxf(v1, 0.f);
                        size_t o = (size_t)row * 1024 + cc;
                        unsigned pk = ((unsigned)f2b_one(a1 * a1) << 16) | f2b_one(a0 * a0);
                        *(unsigned*)((bf16r*)outv + o) = pk;
                    } else {
                        size_t o = (size_t)row * 256 + (cc - 1024);
                        float s0 = 1.0f / (1.0f + __expf(-v0));
                        float s1 = 1.0f / (1.0f + __expf(-v1));
                        unsigned pk = ((unsigned)f2b_one(s1) << 16) | f2b_one(s0);
                        *(unsigned*)((bf16r*)out2v + o) = pk;
                    }
                }
            }
        }
    }
}

// ---------------- WKV (chunked 3-pass, 2 channels/thread, 32-bit loads) -------------
// CHUNK=64 -> 512 blocks x 128 threads for pass1/pass3.
__global__ void wkv_pass1(const bf16r* __restrict__ kvr, const float* __restrict__ decay)
{
    int b  = blockIdx.x >> 6;            // / NCHUNK
    int ch = blockIdx.x & (NCHUNK - 1);
    int c  = threadIdx.x * 2;
    float w0 = decay[c]     * (1.0f / Tz);
    float w1 = decay[c + 1] * (1.0f / Tz);
    float ew0 = __expf(w0), ew1 = __expf(w1);
    size_t base = (size_t)(b * Tz + ch * CHUNK) * NKVR + c;
    float a0 = 0.f, b0 = 0.f, a1 = 0.f, b1 = 0.f;
    #pragma unroll 8
    for (int i = 0; i < CHUNK; i++) {
        unsigned kp = *(const unsigned*)(kvr + base + (size_t)i * NKVR);
        unsigned vp = *(const unsigned*)(kvr + base + 256 + (size_t)i * NKVR);
        float e0 = __expf(b2f((bf16r)(kp & 0xFFFFu)));
        float e1 = __expf(b2f((bf16r)(kp >> 16)));
        float v0 = b2f((bf16r)(vp & 0xFFFFu));
        float v1 = b2f((bf16r)(vp >> 16));
        a0 = fmaf(ew0, a0, e0 * v0);  b0 = fmaf(ew0, b0, e0);
        a1 = fmaf(ew1, a1, e1 * v1);  b1 = fmaf(ew1, b1, e1);
    }
    int o = ch * (Bz * Cz) + b * Cz + c;
    g_cA[o] = a0; g_cA[o + 1] = a1;
    g_cB[o] = b0; g_cB[o + 1] = b1;
}

__global__ void wkv_pass2(const float* __restrict__ decay)
{
    int idx = blockIdx.x * blockDim.x + threadIdx.x;   // Bz*Cz threads
    int c = idx & (Cz - 1);
    float w   = decay[c] * (1.0f / Tz);
    float ewL = __expf(w * CHUNK);
    float a = 0.f, bb = 0.f;
    #pragma unroll 8
    for (int ch = 0; ch < NCHUNK; ch++) {
        int o = ch * (Bz * Cz) + idx;
        g_a0[o] = a;
        g_b0[o] = bb;
        a  = fmaf(ewL, a,  g_cA[o]);
        bb = fmaf(ewL, bb, g_cB[o]);
    }
}

__global__ void wkv_pass3(const bf16r* __restrict__ kvr,
                          const float* __restrict__ decay, const float* __restrict__ first,
                          bf16r* __restrict__ hb)
{
    int b  = blockIdx.x >> 6;
    int ch = blockIdx.x & (NCHUNK - 1);
    int c  = threadIdx.x * 2;
    float w0 = decay[c]     * (1.0f / Tz);
    float w1 = decay[c + 1] * (1.0f / Tz);
    float u0 = first[c]     * (1.0f / Tz);
    float u1 = first[c + 1] * (1.0f / Tz);
    float ew0 = __expf(w0), ew1 = __expf(w1);
    float eu0 = __expf(u0), eu1 = __expf(u1);
    int co = ch * (Bz * Cz) + b * Cz + c;
    float a0 = g_a0[co], b0 = g_b0[co];
    float a1 = g_a0[co + 1], b1 = g_b0[co + 1];
    int t0 = b * Tz + ch * CHUNK;
    size_t base = (size_t)t0 * NKVR + c;
    size_t ob   = (size_t)t0 * Cz + c;
    #pragma unroll 8
    for (int i = 0; i < CHUNK; i++) {
        unsigned kp = *(const unsigned*)(kvr + base + (size_t)i * NKVR);
        unsigned vp = *(const unsigned*)(kvr + base + 256 + (size_t)i * NKVR);
        unsigned rp = *(const unsigned*)(kvr + base + 512 + (size_t)i * NKVR);
        float e0 = __expf(b2f((bf16r)(kp & 0xFFFFu)));
        float e1 = __expf(b2f((bf16r)(kp >> 16)));
        float v0 = b2f((bf16r)(vp & 0xFFFFu));
        float v1 = b2f((bf16r)(vp >> 16));
        float r0 = b2f((bf16r)(rp & 0xFFFFu));
        float r1 = b2f((bf16r)(rp >> 16));
        float q0 = eu0 * e0, q1 = eu1 * e1;
        float y0 = __fdividef(fmaf(q0, v0, a0), b0 + q0);
        float y1 = __fdividef(fmaf(q1, v1, a1), b1 + q1);
        float s0 = 1.0f / (1.0f + __expf(-r0));
        float s1 = 1.0f / (1.0f + __expf(-r1));
        unsigned pk = ((unsigned)f2b_one(s1 * y1) << 16) | f2b_one(s0 * y0);
        *(unsigned*)(hb + ob + (size_t)i * Cz) = pk;
        a0 = fmaf(ew0, a0, e0 * v0);  b0 = fmaf(ew0, b0, e0);
        a1 = fmaf(ew1, a1, e1 * v1);  b1 = fmaf(ew1, b1, e1);
    }
}

// ---------------- launch ----------------
extern "C" void kernel_launch(void* const* d_in, const int* in_sizes, int n_in,
                              void* d_out, int out_size)
{
    const float* x      = (const float*)d_in[0];
    const float* Wk     = (const float*)d_in[1];
    const float* Wv     = (const float*)d_in[2];
    const float* Wr     = (const float*)d_in[3];
    const float* Wo     = (const float*)d_in[4];
    const float* Wk_ffn = (const float*)d_in[5];
    const float* Wv_ffn = (const float*)d_in[6];
    const float* Wr_ffn = (const float*)d_in[7];
    const float* g1     = (const float*)d_in[8];
    const float* b1     = (const float*)d_in[9];
    const float* g2     = (const float*)d_in[10];
    const float* b2     = (const float*)d_in[11];
    const float* decay  = (const float*)d_in[12];
    const float* first  = (const float*)d_in[13];
    float* out = (float*)d_out;

    bf16r *kvrb, *srb, *hb, *h2b, *kkb, *wkvr, *wf1, *wo, *wvf;
    cudaGetSymbolAddress((void**)&kvrb, g_kvrb);
    cudaGetSymbolAddress((void**)&srb,  g_srb);
    cudaGetSymbolAddress((void**)&hb,   g_hb);
    cudaGetSymbolAddress((void**)&h2b,  g_h2b);
    cudaGetSymbolAddress((void**)&kkb,  g_kkb);
    cudaGetSymbolAddress((void**)&wkvr, g_wkvr);
    cudaGetSymbolAddress((void**)&wf1,  g_wf1);
    cudaGetSymbolAddress((void**)&wo,   g_wo);
    cudaGetSymbolAddress((void**)&wvf,  g_wvf);

    cudaFuncSetAttribute(gemm_w32_kernel,
                         cudaFuncAttributeMaxDynamicSharedMemorySize, GSM_TOTAL);
    cudaFuncSetAttribute(gemm_w64_kernel,
                         cudaFuncAttributeMaxDynamicSharedMemorySize, GSM_TOTAL);

    dim3 gKVR(BTz / 128, NKVR / 128);   // (256, 6)
    dim3 g256(BTz / 128, Cz   / 128);   // (256, 2)
    dim3 gFF1(BTz / 128, NFF1 / 128);   // (256, 10)

    // ---- SpatialMix ----
    ln_kernel<<<BTz / 4, 128>>>(x, g1, b1, hb);                              // 1
    pack_all_kernel<<<PK_ALL / 256, 256>>>(Wk, Wv, Wr, Wk_ffn, Wr_ffn,       // 2
                                           Wo, Wv_ffn, wkvr, wf1, wo, wvf);
    gemm_w64_kernel<<<gKVR, 128, GSM_TOTAL>>>(hb, wkvr, kvrb,                // 3
                                              nullptr, Cz, NKVR, 0);

    wkv_pass1<<<Bz * NCHUNK, 128>>>(kvrb, decay);                            // 4 (profiled)
    wkv_pass2<<<Bz, Cz>>>(decay);                                            // 5
    wkv_pass3<<<Bz * NCHUNK, 128>>>(kvrb, decay, first, hb);                 // 6  hb := bf16(sr*y)

    gemm_w32_kernel<<<g256, 256, GSM_TOTAL>>>(hb, wo, out, x,                // 7
                                              nullptr, nullptr, Cz, Cz, 3);

    // ---- ChannelMix ----
    ln_kernel<<<BTz / 4, 128>>>(out, g2, b2, h2b);                           // 8
    gemm_w64_kernel<<<gFF1, 128, GSM_TOTAL>>>(h2b, wf1, kkb,                 // 9
                                              srb, Cz, NFF1, 5);
    gemm_w32_kernel<<<g256, 256, GSM_TOTAL>>>(kkb, wvf, out, out, srb,       // 10
                                              nullptr, HIDz, Cz, 4);
    (void)in_sizes; (void)n_in; (void)out_size;
}

// round 17
// speedup vs baseline: 1.1596x; 1.1596x over previous
#include <cuda_runtime.h>
#include <cuda_bf16.h>
#include <math.h>

// Problem dims (fixed by the reference)
#define Bz      8
#define Tz      4096
#define Cz      256
#define HIDz    1024
#define BTz     (Bz*Tz)          // 32768 tokens
#define CHUNK   64
#define NCHUNK  (Tz/CHUNK)       // 64
#define NKVR    768              // k|v|r packed width
#define NFF1    1280             // ffn_k|ffn_r packed width

typedef unsigned short bf16r;    // raw bf16 bits

__device__ __forceinline__ bf16r f2b_one(float f) {
    __nv_bfloat16 b = __float2bfloat16(f);
    return *(bf16r*)&b;
}
__device__ __forceinline__ float b2f(bf16r r) {
    return __uint_as_float((unsigned)r << 16);
}

// ---------------- scratch (static __device__, no allocs) ----------------
__device__ bf16r g_kvrb[(size_t)BTz*NKVR]; // bf16 k|v|r(pre-sigmoid), 48MB
__device__ bf16r g_srb [(size_t)BTz*Cz];   // FFN gate (sigmoid), bf16
__device__ bf16r g_hb  [(size_t)BTz*Cz];   // bf16 LN1 out, later bf16(sr*y)
__device__ bf16r g_h2b [(size_t)BTz*Cz];   // bf16 LN2 out
__device__ bf16r g_kkb [(size_t)BTz*HIDz]; // bf16 FFN hidden
__device__ float g_cA [Bz*Cz*NCHUNK];
__device__ float g_cB [Bz*Cz*NCHUNK];
__device__ float g_a0 [Bz*Cz*NCHUNK];
__device__ float g_b0 [Bz*Cz*NCHUNK];
// packed bf16 weights, TRANSPOSED: [N, K] row-major
__device__ bf16r g_wkvr[NKVR*Cz];          // (Wk|Wv|Wr)^T : [768,256]
__device__ bf16r g_wf1 [NFF1*Cz];          // (Wk_ffn|Wr_ffn)^T : [1280,256]
__device__ bf16r g_wo  [Cz*Cz];            // Wo^T : [256,256]
__device__ bf16r g_wvf [Cz*HIDz];          // Wv_ffn^T : [256,1024]

// ---------------- LN (device helper, one warp per token) ----------------
__device__ __forceinline__ void ln_warp(const float* __restrict__ x,
                                        const float* __restrict__ g,
                                        const float* __restrict__ b,
                                        bf16r* __restrict__ out,
                                        size_t token, int lane)
{
    size_t base = token * Cz + lane * 8;
    float4 v0 = *(const float4*)(x + base);
    float4 v1 = *(const float4*)(x + base + 4);
    float s  = v0.x + v0.y + v0.z + v0.w + v1.x + v1.y + v1.z + v1.w;
    float s2 = v0.x*v0.x + v0.y*v0.y + v0.z*v0.z + v0.w*v0.w
             + v1.x*v1.x + v1.y*v1.y + v1.z*v1.z + v1.w*v1.w;
    #pragma unroll
    for (int off = 16; off; off >>= 1) {
        s  += __shfl_xor_sync(0xffffffffu, s,  off);
        s2 += __shfl_xor_sync(0xffffffffu, s2, off);
    }
    float m   = s  * (1.0f / Cz);
    float var = s2 * (1.0f / Cz) - m * m;
    float rs  = rsqrtf(var + 1e-5f);
    float4 g0 = *(const float4*)(g + lane * 8);
    float4 g1 = *(const float4*)(g + lane * 8 + 4);
    float4 b0 = *(const float4*)(b + lane * 8);
    float4 b1 = *(const float4*)(b + lane * 8 + 4);
    uint4 o;
    o.x = ((unsigned)f2b_one((v0.y - m) * rs * g0.y + b0.y) << 16) | f2b_one((v0.x - m) * rs * g0.x + b0.x);
    o.y = ((unsigned)f2b_one((v0.w - m) * rs * g0.w + b0.w) << 16) | f2b_one((v0.z - m) * rs * g0.z + b0.z);
    o.z = ((unsigned)f2b_one((v1.y - m) * rs * g1.y + b1.y) << 16) | f2b_one((v1.x - m) * rs * g1.x + b1.x);
    o.w = ((unsigned)f2b_one((v1.w - m) * rs * g1.w + b1.w) << 16) | f2b_one((v1.z - m) * rs * g1.z + b1.z);
    *(uint4*)(out + base) = o;
}

// ---------------- plain LN kernel (LN2) ----------------
__global__ void __launch_bounds__(128)
ln_kernel(const float* __restrict__ x,
          const float* __restrict__ g,
          const float* __restrict__ b,
          bf16r* __restrict__ out)
{
    ln_warp(x, g, b, out, (size_t)blockIdx.x * 4 + (threadIdx.x >> 5), threadIdx.x & 31);
}

// ---------------- merged LN1 + weight pack kernel ----------------
#define PK_KVR (NKVR*Cz)
#define PK_F1  (NFF1*Cz)
#define PK_WO  (Cz*Cz)
#define PK_WVF (HIDz*Cz)
#define PK_ALL (PK_KVR + PK_F1 + PK_WO + PK_WVF)   // 851968
#define LN_BLKS (BTz / 4)                           // 8192 (128-thr blocks)
#define PK_BLKS (PK_ALL / 128)                      // 6656
__global__ void __launch_bounds__(128)
lnpack_kernel(const float* __restrict__ x,
              const float* __restrict__ g1,
              const float* __restrict__ b1,
              bf16r* __restrict__ hb,
              const float* __restrict__ Wk,
              const float* __restrict__ Wv,
              const float* __restrict__ Wr,
              const float* __restrict__ Wkf,
              const float* __restrict__ Wrf,
              const float* __restrict__ Wo,
              const float* __restrict__ Wvf,
              bf16r* __restrict__ okvr,
              bf16r* __restrict__ of1,
              bf16r* __restrict__ owo,
              bf16r* __restrict__ owvf)
{
    if (blockIdx.x < LN_BLKS) {
        ln_warp(x, g1, b1, hb,
                (size_t)blockIdx.x * 4 + (threadIdx.x >> 5), threadIdx.x & 31);
        return;
    }
    int i = (blockIdx.x - LN_BLKS) * 128 + threadIdx.x;
    if (i < PK_KVR) {
        int n = i / Cz, k = i % Cz;
        float v = (n < 256) ? Wk[k * 256 + n]
                : (n < 512) ? Wv[k * 256 + (n - 256)]
                            : Wr[k * 256 + (n - 512)];
        okvr[i] = f2b_one(v);
    } else if (i < PK_KVR + PK_F1) {
        int j = i - PK_KVR;
        int n = j / Cz, k = j % Cz;
        float v = (n < 1024) ? Wkf[k * 1024 + n] : Wrf[k * 256 + (n - 1024)];
        of1[j] = f2b_one(v);
    } else if (i < PK_KVR + PK_F1 + PK_WO) {
        int j = i - PK_KVR - PK_F1;
        int n = j / Cz, k = j % Cz;
        owo[j] = f2b_one(Wo[k * 256 + n]);
    } else {
        int j = i - PK_KVR - PK_F1 - PK_WO;
        int n = j / HIDz, k = j % HIDz;
        owvf[j] = f2b_one(Wvf[(size_t)k * 256 + n]);
    }
}

// ---------------- async-copy / ldmatrix helpers ----------------
__device__ __forceinline__ void cp16(void* sdst, const void* gsrc) {
    unsigned d = (unsigned)__cvta_generic_to_shared(sdst);
    asm volatile("cp.async.cg.shared.global [%0], [%1], 16;" :: "r"(d), "l"(gsrc));
}
__device__ __forceinline__ void ldsm_x4(unsigned& r0, unsigned& r1, unsigned& r2, unsigned& r3,
                                        const void* p) {
    unsigned a = (unsigned)__cvta_generic_to_shared(p);
    asm volatile("ldmatrix.sync.aligned.m8n8.x4.shared.b16 {%0,%1,%2,%3}, [%4];"
                 : "=r"(r0), "=r"(r1), "=r"(r2), "=r"(r3) : "r"(a));
}

// ---------------- bf16 tensor-core GEMM (R8 winner, templated on NK / MODE) --------
// BM=128, BN=128, BK=64, 2-stage cp.async (dynamic smem 64KB, XOR-swizzled 128B rows),
// 256 threads = 8 warps (4x2), warp tile 32x64, forced 2 CTAs/SM (128 regs).
// MODE: 0 bf16 plain, 3 fp32 res+acc, 4 fp32 res + bf16gate*acc,
//       5 split: col<1024 -> bf16 relu^2 (width 1024); else bf16 sigmoid (out2, width 256)
#define GSM_STAGE 16384            // one 128x64 bf16 tile, 128B rows
#define GSM_TOTAL 65536            // A0,A1,B0,B1
template<int NK, int MODE>
__global__ void __launch_bounds__(256, 2)
gemm_tpl(const bf16r* __restrict__ A,
         const bf16r* __restrict__ BT,
         void* __restrict__ outv,
         const float* __restrict__ res,
         const bf16r* __restrict__ gate,
         void* __restrict__ out2v,
         int N)
{
    const int K = NK * 64;
    extern __shared__ char smem[];
    char* sA[2] = { smem,               smem + GSM_STAGE };
    char* sB[2] = { smem + 2*GSM_STAGE, smem + 3*GSM_STAGE };

    int tid  = threadIdx.x;
    int lane = tid & 31;
    int warp = tid >> 5;
    int wm = (warp & 3) * 32;
    int wn = (warp >> 2) * 64;
    int blockRow = blockIdx.x * 128;
    int blockCol = blockIdx.y * 128;

    const bf16r* Ab = A  + (size_t)blockRow * K;
    const bf16r* Bb = BT + (size_t)blockCol * K;

    float acc[2][8][4];
    #pragma unroll
    for (int i = 0; i < 2; i++)
        #pragma unroll
        for (int j = 0; j < 8; j++)
            #pragma unroll
            for (int l = 0; l < 4; l++) acc[i][j][l] = 0.f;

    #pragma unroll
    for (int it = 0; it < 4; it++) {
        int idx = tid + it * 256;
        int r = idx >> 3, c8 = idx & 7;
        unsigned so = (unsigned)r * 128u + (unsigned)((c8 ^ (r & 7)) * 16);
        cp16(sA[0] + so, Ab + (size_t)r * K + c8 * 8);
        cp16(sB[0] + so, Bb + (size_t)r * K + c8 * 8);
    }
    asm volatile("cp.async.commit_group;");

    int a_row = wm + (lane & 15);
    int a_half = lane >> 4;
    int b_grp = lane >> 3;
    int b_row = wn + (b_grp >> 1) * 8 + (lane & 7);
    int b_half = b_grp & 1;

    for (int kb = 0; kb < NK; kb++) {
        int buf = kb & 1;
        if (kb + 1 < NK) {
            int ko = (kb + 1) << 6;
            #pragma unroll
            for (int it = 0; it < 4; it++) {
                int idx = tid + it * 256;
                int r = idx >> 3, c8 = idx & 7;
                unsigned so = (unsigned)r * 128u + (unsigned)((c8 ^ (r & 7)) * 16);
                cp16(sA[buf ^ 1] + so, Ab + (size_t)r * K + ko + c8 * 8);
                cp16(sB[buf ^ 1] + so, Bb + (size_t)r * K + ko + c8 * 8);
            }
            asm volatile("cp.async.commit_group;");
            asm volatile("cp.async.wait_group 1;");
        } else {
            asm volatile("cp.async.wait_group 0;");
        }
        __syncthreads();

        #pragma unroll
        for (int k16 = 0; k16 < 4; k16++) {
            unsigned af[2][4], bfr[4][4];
            int ac8 = k16 * 2 + a_half;
            int bc8 = k16 * 2 + b_half;
            #pragma unroll
            for (int sm = 0; sm < 2; sm++) {
                int r = a_row + sm * 16;
                ldsm_x4(af[sm][0], af[sm][1], af[sm][2], af[sm][3],
                        sA[buf] + (unsigned)r * 128u + (unsigned)((ac8 ^ (r & 7)) * 16));
            }
            #pragma unroll
            for (int pr = 0; pr < 4; pr++) {
                int r = b_row + pr * 16;
                ldsm_x4(bfr[pr][0], bfr[pr][1], bfr[pr][2], bfr[pr][3],
                        sB[buf] + (unsigned)r * 128u + (unsigned)((bc8 ^ (r & 7)) * 16));
            }
            #pragma unroll
            for (int sm = 0; sm < 2; sm++)
                #pragma unroll
                for (int sn = 0; sn < 8; sn++) {
                    int pr = sn >> 1, q = (sn & 1) * 2;
                    asm volatile(
                        "mma.sync.aligned.m16n8k16.row.col.f32.bf16.bf16.f32 "
                        "{%0,%1,%2,%3}, {%4,%5,%6,%7}, {%8,%9}, {%0,%1,%2,%3};"
                        : "+f"(acc[sm][sn][0]), "+f"(acc[sm][sn][1]),
                          "+f"(acc[sm][sn][2]), "+f"(acc[sm][sn][3])
                        : "r"(af[sm][0]), "r"(af[sm][1]), "r"(af[sm][2]), "r"(af[sm][3]),
                          "r"(bfr[pr][q]), "r"(bfr[pr][q + 1]));
                }
        }
        if (kb + 1 < NK) __syncthreads();
    }

    #pragma unroll
    for (int sm = 0; sm < 2; sm++) {
        #pragma unroll
        for (int sn = 0; sn < 8; sn++) {
            int r0 = blockRow + wm + sm * 16 + (lane >> 2);
            int cc = blockCol + wn + sn * 8 + (lane & 3) * 2;
            #pragma unroll
            for (int half = 0; half < 2; half++) {
                int row = r0 + half * 8;
                float v0 = acc[sm][sn][half * 2 + 0];
                float v1 = acc[sm][sn][half * 2 + 1];
                if (MODE == 0) {
                    size_t o = (size_t)row * N + cc;
                    unsigned pk = ((unsigned)f2b_one(v1) << 16) | f2b_one(v0);
                    *(unsigned*)((bf16r*)outv + o) = pk;
                } else if (MODE == 3) {
                    size_t o = (size_t)row * N + cc;
                    v0 += res[o]; v1 += res[o + 1];
                    *(float2*)((float*)outv + o) = make_float2(v0, v1);
                } else if (MODE == 4) {
                    size_t o = (size_t)row * N + cc;
                    unsigned gp = *(const unsigned*)(gate + o);
                    v0 = res[o]     + b2f((bf16r)(gp & 0xFFFFu)) * v0;
                    v1 = res[o + 1] + b2f((bf16r)(gp >> 16))     * v1;
                    *(float2*)((float*)outv + o) = make_float2(v0, v1);
                } else { // MODE 5 split
                    if (cc < 1024) {
                        float a0 = fmaxf(v0, 0.f), a1 = fmaxf(v1, 0.f);
                        size_t o = (size_t)row * 1024 + cc;
                        unsigned pk = ((unsigned)f2b_one(a1 * a1) << 16) | f2b_one(a0 * a0);
                        *(unsigned*)((bf16r*)outv + o) = pk;
                    } else {
                        size_t o = (size_t)row * 256 + (cc - 1024);
                        float s0 = 1.0f / (1.0f + __expf(-v0));
                        float s1 = 1.0f / (1.0f + __expf(-v1));
                        unsigned pk = ((unsigned)f2b_one(s1) << 16) | f2b_one(s0);
                        *(unsigned*)((bf16r*)out2v + o) = pk;
                    }
                }
            }
        }
    }
}

// ---------------- WKV (chunked 3-pass, 2 channels/thread, 32-bit loads) -------------
// CHUNK=64 -> 512 blocks x 128 threads for pass1/pass3.
__global__ void wkv_pass1(const bf16r* __restrict__ kvr, const float* __restrict__ decay)
{
    int b  = blockIdx.x >> 6;            // / NCHUNK
    int ch = blockIdx.x & (NCHUNK - 1);
    int c  = threadIdx.x * 2;
    float w0 = decay[c]     * (1.0f / Tz);
    float w1 = decay[c + 1] * (1.0f / Tz);
    float ew0 = __expf(w0), ew1 = __expf(w1);
    size_t base = (size_t)(b * Tz + ch * CHUNK) * NKVR + c;
    float a0 = 0.f, b0 = 0.f, a1 = 0.f, b1 = 0.f;
    #pragma unroll 8
    for (int i = 0; i < CHUNK; i++) {
        unsigned kp = *(const unsigned*)(kvr + base + (size_t)i * NKVR);
        unsigned vp = *(const unsigned*)(kvr + base + 256 + (size_t)i * NKVR);
        float e0 = __expf(b2f((bf16r)(kp & 0xFFFFu)));
        float e1 = __expf(b2f((bf16r)(kp >> 16)));
        float v0 = b2f((bf16r)(vp & 0xFFFFu));
        float v1 = b2f((bf16r)(vp >> 16));
        a0 = fmaf(ew0, a0, e0 * v0);  b0 = fmaf(ew0, b0, e0);
        a1 = fmaf(ew1, a1, e1 * v1);  b1 = fmaf(ew1, b1, e1);
    }
    int o = ch * (Bz * Cz) + b * Cz + c;
    g_cA[o] = a0; g_cA[o + 1] = a1;
    g_cB[o] = b0; g_cB[o + 1] = b1;
}

__global__ void wkv_pass2(const float* __restrict__ decay)
{
    int idx = blockIdx.x * blockDim.x + threadIdx.x;   // Bz*Cz threads
    int c = idx & (Cz - 1);
    float w   = decay[c] * (1.0f / Tz);
    float ewL = __expf(w * CHUNK);
    float a = 0.f, bb = 0.f;
    #pragma unroll 8
    for (int ch = 0; ch < NCHUNK; ch++) {
        int o = ch * (Bz * Cz) + idx;
        g_a0[o] = a;
        g_b0[o] = bb;
        a  = fmaf(ewL, a,  g_cA[o]);
        bb = fmaf(ewL, bb, g_cB[o]);
    }
}

__global__ void wkv_pass3(const bf16r* __restrict__ kvr,
                          const float* __restrict__ decay, const float* __restrict__ first,
                          bf16r* __restrict__ hb)
{
    int b  = blockIdx.x >> 6;
    int ch = blockIdx.x & (NCHUNK - 1);
    int c  = threadIdx.x * 2;
    float w0 = decay[c]     * (1.0f / Tz);
    float w1 = decay[c + 1] * (1.0f / Tz);
    float u0 = first[c]     * (1.0f / Tz);
    float u1 = first[c + 1] * (1.0f / Tz);
    float ew0 = __expf(w0), ew1 = __expf(w1);
    float eu0 = __expf(u0), eu1 = __expf(u1);
    int co = ch * (Bz * Cz) + b * Cz + c;
    float a0 = g_a0[co], b0 = g_b0[co];
    float a1 = g_a0[co + 1], b1 = g_b0[co + 1];
    int t0 = b * Tz + ch * CHUNK;
    size_t base = (size_t)t0 * NKVR + c;
    size_t ob   = (size_t)t0 * Cz + c;
    #pragma unroll 8
    for (int i = 0; i < CHUNK; i++) {
        unsigned kp = *(const unsigned*)(kvr + base + (size_t)i * NKVR);
        unsigned vp = *(const unsigned*)(kvr + base + 256 + (size_t)i * NKVR);
        unsigned rp = *(const unsigned*)(kvr + base + 512 + (size_t)i * NKVR);
        float e0 = __expf(b2f((bf16r)(kp & 0xFFFFu)));
        float e1 = __expf(b2f((bf16r)(kp >> 16)));
        float v0 = b2f((bf16r)(vp & 0xFFFFu));
        float v1 = b2f((bf16r)(vp >> 16));
        float r0 = b2f((bf16r)(rp & 0xFFFFu));
        float r1 = b2f((bf16r)(rp >> 16));
        float q0 = eu0 * e0, q1 = eu1 * e1;
        float y0 = __fdividef(fmaf(q0, v0, a0), b0 + q0);
        float y1 = __fdividef(fmaf(q1, v1, a1), b1 + q1);
        float s0 = 1.0f / (1.0f + __expf(-r0));
        float s1 = 1.0f / (1.0f + __expf(-r1));
        unsigned pk = ((unsigned)f2b_one(s1 * y1) << 16) | f2b_one(s0 * y0);
        *(unsigned*)(hb + ob + (size_t)i * Cz) = pk;
        a0 = fmaf(ew0, a0, e0 * v0);  b0 = fmaf(ew0, b0, e0);
        a1 = fmaf(ew1, a1, e1 * v1);  b1 = fmaf(ew1, b1, e1);
    }
}

// ---------------- launch ----------------
extern "C" void kernel_launch(void* const* d_in, const int* in_sizes, int n_in,
                              void* d_out, int out_size)
{
    const float* x      = (const float*)d_in[0];
    const float* Wk     = (const float*)d_in[1];
    const float* Wv     = (const float*)d_in[2];
    const float* Wr     = (const float*)d_in[3];
    const float* Wo     = (const float*)d_in[4];
    const float* Wk_ffn = (const float*)d_in[5];
    const float* Wv_ffn = (const float*)d_in[6];
    const float* Wr_ffn = (const float*)d_in[7];
    const float* g1     = (const float*)d_in[8];
    const float* b1     = (const float*)d_in[9];
    const float* g2     = (const float*)d_in[10];
    const float* b2     = (const float*)d_in[11];
    const float* decay  = (const float*)d_in[12];
    const float* first  = (const float*)d_in[13];
    float* out = (float*)d_out;

    bf16r *kvrb, *srb, *hb, *h2b, *kkb, *wkvr, *wf1, *wo, *wvf;
    cudaGetSymbolAddress((void**)&kvrb, g_kvrb);
    cudaGetSymbolAddress((void**)&srb,  g_srb);
    cudaGetSymbolAddress((void**)&hb,   g_hb);
    cudaGetSymbolAddress((void**)&h2b,  g_h2b);
    cudaGetSymbolAddress((void**)&kkb,  g_kkb);
    cudaGetSymbolAddress((void**)&wkvr, g_wkvr);
    cudaGetSymbolAddress((void**)&wf1,  g_wf1);
    cudaGetSymbolAddress((void**)&wo,   g_wo);
    cudaGetSymbolAddress((void**)&wvf,  g_wvf);

    cudaFuncSetAttribute(gemm_tpl<4, 0>,
                         cudaFuncAttributeMaxDynamicSharedMemorySize, GSM_TOTAL);
    cudaFuncSetAttribute(gemm_tpl<4, 3>,
                         cudaFuncAttributeMaxDynamicSharedMemorySize, GSM_TOTAL);
    cudaFuncSetAttribute(gemm_tpl<4, 5>,
                         cudaFuncAttributeMaxDynamicSharedMemorySize, GSM_TOTAL);
    cudaFuncSetAttribute(gemm_tpl<16, 4>,
                         cudaFuncAttributeMaxDynamicSharedMemorySize, GSM_TOTAL);

    dim3 gKVR(BTz / 128, NKVR / 128);   // (256, 6)
    dim3 g256(BTz / 128, Cz   / 128);   // (256, 2)
    dim3 gFF1(BTz / 128, NFF1 / 128);   // (256, 10)

    // ---- SpatialMix ----
    lnpack_kernel<<<LN_BLKS + PK_BLKS, 128>>>(x, g1, b1, hb,                 // 1
        Wk, Wv, Wr, Wk_ffn, Wr_ffn, Wo, Wv_ffn, wkvr, wf1, wo, wvf);
    gemm_tpl<4, 0><<<gKVR, 256, GSM_TOTAL>>>(hb, wkvr, kvrb,                 // 2
                                             nullptr, nullptr, nullptr, NKVR);

    wkv_pass1<<<Bz * NCHUNK, 128>>>(kvrb, decay);                            // 3
    wkv_pass2<<<Bz, Cz>>>(decay);                                            // 4 (profiled)
    wkv_pass3<<<Bz * NCHUNK, 128>>>(kvrb, decay, first, hb);                 // 5  hb := bf16(sr*y)

    gemm_tpl<4, 3><<<g256, 256, GSM_TOTAL>>>(hb, wo, out, x,                 // 6
                                             nullptr, nullptr, Cz);

    // ---- ChannelMix ----
    ln_kernel<<<BTz / 4, 128>>>(out, g2, b2, h2b);                           // 7
    gemm_tpl<4, 5><<<gFF1, 256, GSM_TOTAL>>>(h2b, wf1, kkb,                  // 8
                                             nullptr, nullptr, srb, NFF1);
    gemm_tpl<16, 4><<<g256, 256, GSM_TOTAL>>>(kkb, wvf, out, out, srb,       // 9
                                              nullptr, Cz);
    (void)in_sizes; (void)n_in; (void)out_size;
}